// round 6
// baseline (speedup 1.0000x reference)
#include <cuda_runtime.h>

// Problem constants (fixed by the reference: B=4, C=32, H=64, W=64, NW=64)
#define NWC 64
#define NPAIR 32
#define HW_PIX 4096
#define CC 32

// Packed f32x2 FMA: d = a*b + c on two fp32 lanes in one FFMA2 instruction.
__device__ __forceinline__ void ffma2(float& dx, float& dy,
                                      float ax, float ay,
                                      float bx, float by,
                                      float cx, float cy) {
    asm("{\n\t"
        ".reg .b64 ra, rb, rc, rd;\n\t"
        "mov.b64 ra, {%2, %3};\n\t"
        "mov.b64 rb, {%4, %5};\n\t"
        "mov.b64 rc, {%6, %7};\n\t"
        "fma.rn.f32x2 rd, ra, rb, rc;\n\t"
        "mov.b64 {%0, %1}, rd;\n\t"
        "}"
        : "=f"(dx), "=f"(dy)
        : "f"(ax), "f"(ay), "f"(bx), "f"(by), "f"(cx), "f"(cy));
}

__device__ __forceinline__ void fadd2(float& dx, float& dy,
                                      float ax, float ay,
                                      float bx, float by) {
    asm("{\n\t"
        ".reg .b64 ra, rb, rd;\n\t"
        "mov.b64 ra, {%2, %3};\n\t"
        "mov.b64 rb, {%4, %5};\n\t"
        "add.rn.f32x2 rd, ra, rb;\n\t"
        "mov.b64 {%0, %1}, rd;\n\t"
        "}"
        : "=f"(dx), "=f"(dy)
        : "f"(ax), "f"(ay), "f"(bx), "f"(by));
}

__device__ __forceinline__ void fmul2(float& dx, float& dy,
                                      float ax, float ay,
                                      float bx, float by) {
    asm("{\n\t"
        ".reg .b64 ra, rb, rd;\n\t"
        "mov.b64 ra, {%2, %3};\n\t"
        "mov.b64 rb, {%4, %5};\n\t"
        "mul.rn.f32x2 rd, ra, rb;\n\t"
        "mov.b64 {%0, %1}, rd;\n\t"
        "}"
        : "=f"(dx), "=f"(dy)
        : "f"(ax), "f"(ay), "f"(bx), "f"(by));
}

__device__ __forceinline__ float ex2(float a) {
    float r;
    asm("ex2.approx.ftz.f32 %0, %1;" : "=f"(r) : "f"(a));
    return r;
}

// Packed polynomial exp2 on the FMA/ALU pipes (MUFU offload).
// Magic-number range reduction + deg-5 Taylor on f in [-0.5, 0.5]
// + exponent-bit scale. Max rel err ~2.4e-6.
__device__ __forceinline__ void exp2poly2(float& ex_, float& ey_, float gx, float gy) {
    const float MAG = 12582912.0f;  // 1.5 * 2^23
    const float C1 = 0.69314718056f, C2 = 0.240226506959f,
                C3 = 0.0555041086648f, C4 = 0.00961812910763f,
                C5 = 0.00133335581464f;
    // clamp: exponents below -126 underflow to ~0; prevents scale-bit wrap
    float gcx = fmaxf(gx, -126.0f);
    float gcy = fmaxf(gy, -126.0f);
    float tx, ty;  fadd2(tx, ty, gcx, gcy, MAG, MAG);        // t = g + MAG  -> i in low bits
    float ux, uy;  fadd2(ux, uy, tx, ty, -MAG, -MAG);        // u = i (as float)
    float fx, fy;  ffma2(fx, fy, ux, uy, -1.0f, -1.0f, gcx, gcy);  // f = g - i
    // per-lane 2^i from t's mantissa bits
    float scx = __int_as_float((__float_as_int(tx) << 23) + 0x3F800000);
    float scy = __int_as_float((__float_as_int(ty) << 23) + 0x3F800000);
    // q = C1 + f(C2 + f(C3 + f(C4 + f C5)))
    float qx, qy;
    ffma2(qx, qy, fx, fy, C5, C5, C4, C4);
    ffma2(qx, qy, fx, fy, qx, qy, C3, C3);
    ffma2(qx, qy, fx, fy, qx, qy, C2, C2);
    ffma2(qx, qy, fx, fy, qx, qy, C1, C1);
    // e = 2^i * (1 + f*q) = scale + (f*scale)*q
    float fsx, fsy; fmul2(fsx, fsy, fx, fy, scx, scy);
    ffma2(ex_, ey_, fsx, fsy, qx, qy, scx, scy);
}

__global__ __launch_bounds__(128)
void cplx_gaussian_rbf_kernel(
    const float* __restrict__ x_real, const float* __restrict__ x_imag,
    const float* __restrict__ w_real, const float* __restrict__ w_imag,
    const float* __restrict__ b_real, const float* __restrict__ b_imag,
    const float* __restrict__ mu_real, const float* __restrict__ mu_imag,
    const float* __restrict__ stddev,
    float* __restrict__ out)
{
    // Center-pair coefficient tables: f32x2 lanes carry (center 2p, center 2p+1).
    __shared__ float4 sA[NPAIR];  // {a0_e, a0_o, a1_e, a1_o}
    __shared__ float4 sB[NPAIR];  // {a2_e, a2_o, a3_e, a3_o}
    __shared__ float4 sW[NPAIR];  // {wr_e, wr_o, wi_e, wi_o}

    const int bc   = blockIdx.x >> 4;        // (b*C + c), 0..127
    const int tile = blockIdx.x & 15;        // 16 tiles of 256 pixels per (b,c)
    const int c    = bc & (CC - 1);
    const int tid  = threadIdx.x;

    if (tid < NPAIR) {
        const float LOG2E = 1.4426950408889634f;
        const int n0 = 2 * tid, n1 = 2 * tid + 1;
        float mur0 = mu_real[n0], mui0 = mu_imag[n0];
        float cc0  = LOG2E * 0.5f / stddev[n0];
        float mur1 = mu_real[n1], mui1 = mu_imag[n1];
        float cc1  = LOG2E * 0.5f / stddev[n1];
        sA[tid] = make_float4(-cc0, -cc1, 2.0f * cc0 * mur0, 2.0f * cc1 * mur1);
        sB[tid] = make_float4(2.0f * cc0 * mui0, 2.0f * cc1 * mui1,
                              -cc0 * (mur0 * mur0 + mui0 * mui0),
                              -cc1 * (mur1 * mur1 + mui1 * mui1));
        sW[tid] = make_float4(w_real[c * NWC + n0], w_real[c * NWC + n1],
                              w_imag[c * NWC + n0], w_imag[c * NWC + n1]);
    }
    __syncthreads();

    // 2 consecutive pixels per thread.
    const int pairIdx = bc * (HW_PIX / 2) + tile * 128 + tid;  // pixel-pair units
    const float2 xr = reinterpret_cast<const float2*>(x_real)[pairIdx];
    const float2 xi = reinterpret_cast<const float2*>(x_imag)[pairIdx];

    const float s0 = fmaf(xr.x, xr.x, xi.x * xi.x);
    const float s1 = fmaf(xr.y, xr.y, xi.y * xi.y);

    float ar0x = 0.0f, ar0y = 0.0f, ai0x = 0.0f, ai0y = 0.0f;  // pixel 0
    float ar1x = 0.0f, ar1y = 0.0f, ai1x = 0.0f, ai1y = 0.0f;  // pixel 1

#pragma unroll 8
    for (int p = 0; p < NPAIR; ++p) {
        const float4 A  = sA[p];
        const float4 Bv = sB[p];
        const float4 Wv = sW[p];

        // arguments for both pixels
        float g0x, g0y, g1x, g1y;
        ffma2(g0x, g0y, s0,   s0,   A.x,  A.y,  Bv.z, Bv.w);
        ffma2(g0x, g0y, xr.x, xr.x, A.z,  A.w,  g0x,  g0y);
        ffma2(g0x, g0y, xi.x, xi.x, Bv.x, Bv.y, g0x,  g0y);
        ffma2(g1x, g1y, s1,   s1,   A.x,  A.y,  Bv.z, Bv.w);
        ffma2(g1x, g1y, xr.y, xr.y, A.z,  A.w,  g1x,  g1y);
        ffma2(g1x, g1y, xi.y, xi.y, Bv.x, Bv.y, g1x,  g1y);

        // hybrid exp2: 13/16 pairs on MUFU, 3/16 on FMA-pipe polynomial
        float r0x, r0y, r1x, r1y;
        const int ph = p & 7;
        if (ph == 3) {
            exp2poly2(r0x, r0y, g0x, g0y);
            exp2poly2(r1x, r1y, g1x, g1y);
        } else if (ph == 6) {
            r0x = ex2(g0x); r0y = ex2(g0y);
            exp2poly2(r1x, r1y, g1x, g1y);
        } else {
            r0x = ex2(g0x); r0y = ex2(g0y);
            r1x = ex2(g1x); r1y = ex2(g1y);
        }

        ffma2(ar0x, ar0y, r0x, r0y, Wv.x, Wv.y, ar0x, ar0y);
        ffma2(ai0x, ai0y, r0x, r0y, Wv.z, Wv.w, ai0x, ai0y);
        ffma2(ar1x, ar1y, r1x, r1y, Wv.x, Wv.y, ar1x, ar1y);
        ffma2(ai1x, ai1y, r1x, r1y, Wv.z, Wv.w, ai1x, ai1y);
    }

    const float br = b_real[c];
    const float bi = b_imag[c];

    // Horizontal add (even+odd centers) + bias; one float4 store (r0,i0,r1,i1).
    float4 o;
    o.x = (ar0x + ar0y) + br;
    o.y = (ai0x + ai0y) + bi;
    o.z = (ar1x + ar1y) + br;
    o.w = (ai1x + ai1y) + bi;
    reinterpret_cast<float4*>(out)[pairIdx] = o;
}

extern "C" void kernel_launch(void* const* d_in, const int* in_sizes, int n_in,
                              void* d_out, int out_size) {
    const float* x_real  = (const float*)d_in[0];
    const float* x_imag  = (const float*)d_in[1];
    const float* w_real  = (const float*)d_in[2];
    const float* w_imag  = (const float*)d_in[3];
    const float* b_real  = (const float*)d_in[4];
    const float* b_imag  = (const float*)d_in[5];
    const float* mu_real = (const float*)d_in[6];
    const float* mu_imag = (const float*)d_in[7];
    const float* stddev  = (const float*)d_in[8];
    float* out = (float*)d_out;

    // 128 (b,c) pairs * 16 tiles = 2048 blocks; 128 threads; 2 pixels/thread
    cplx_gaussian_rbf_kernel<<<2048, 128>>>(
        x_real, x_imag, w_real, w_imag, b_real, b_imag,
        mu_real, mu_imag, stddev, out);
}

// round 7
// speedup vs baseline: 1.1597x; 1.1597x over previous
#include <cuda_runtime.h>

// Problem constants (fixed by the reference: B=4, C=32, H=64, W=64, NW=64)
#define NWC 64
#define NPAIR 32
#define HW_PIX 4096
#define CC 32

// Packed f32x2 FMA: d = a*b + c on two fp32 lanes in one FFMA2 instruction.
__device__ __forceinline__ void ffma2(float& dx, float& dy,
                                      float ax, float ay,
                                      float bx, float by,
                                      float cx, float cy) {
    asm("{\n\t"
        ".reg .b64 ra, rb, rc, rd;\n\t"
        "mov.b64 ra, {%2, %3};\n\t"
        "mov.b64 rb, {%4, %5};\n\t"
        "mov.b64 rc, {%6, %7};\n\t"
        "fma.rn.f32x2 rd, ra, rb, rc;\n\t"
        "mov.b64 {%0, %1}, rd;\n\t"
        "}"
        : "=f"(dx), "=f"(dy)
        : "f"(ax), "f"(ay), "f"(bx), "f"(by), "f"(cx), "f"(cy));
}

__device__ __forceinline__ float ex2(float a) {
    float r;
    asm("ex2.approx.ftz.f32 %0, %1;" : "=f"(r) : "f"(a));
    return r;
}

__global__ __launch_bounds__(128)
void cplx_gaussian_rbf_kernel(
    const float* __restrict__ x_real, const float* __restrict__ x_imag,
    const float* __restrict__ w_real, const float* __restrict__ w_imag,
    const float* __restrict__ b_real, const float* __restrict__ b_imag,
    const float* __restrict__ mu_real, const float* __restrict__ mu_imag,
    const float* __restrict__ stddev,
    float* __restrict__ out)
{
    // Center-pair coefficient tables: f32x2 lanes carry (center 2p, center 2p+1),
    // so 3 broadcast LDS.128 serve 2 centers x 4 pixels = 8 evals.
    __shared__ float4 sA[NPAIR];  // {a0_e, a0_o, a1_e, a1_o}
    __shared__ float4 sB[NPAIR];  // {a2_e, a2_o, a3_e, a3_o}
    __shared__ float4 sW[NPAIR];  // {wr_e, wr_o, wi_e, wi_o}

    const int bc   = blockIdx.x >> 3;        // (b*C + c), 0..127
    const int tile = blockIdx.x & 7;         // 8 tiles of 512 pixels per (b,c)
    const int c    = bc & (CC - 1);
    const int tid  = threadIdx.x;

    if (tid < NPAIR) {
        const float LOG2E = 1.4426950408889634f;
        const int n0 = 2 * tid, n1 = 2 * tid + 1;
        // exp(-d2/(2*sigma)) = exp2( a0*s + a1*xr + a2*xi + a3 ),  s = xr^2+xi^2
        float mur0 = mu_real[n0], mui0 = mu_imag[n0];
        float cc0  = LOG2E * 0.5f / stddev[n0];
        float mur1 = mu_real[n1], mui1 = mu_imag[n1];
        float cc1  = LOG2E * 0.5f / stddev[n1];
        sA[tid] = make_float4(-cc0, -cc1, 2.0f * cc0 * mur0, 2.0f * cc1 * mur1);
        sB[tid] = make_float4(2.0f * cc0 * mui0, 2.0f * cc1 * mui1,
                              -cc0 * (mur0 * mur0 + mui0 * mui0),
                              -cc1 * (mur1 * mur1 + mui1 * mui1));
        sW[tid] = make_float4(w_real[c * NWC + n0], w_real[c * NWC + n1],
                              w_imag[c * NWC + n0], w_imag[c * NWC + n1]);
    }
    __syncthreads();

    // 4 consecutive pixels per thread (one float4 load per input).
    const int f4idx    = bc * (HW_PIX / 4) + tile * 128 + tid;  // float4 units
    const int pairBase = f4idx * 2;                              // pixel-pair units

    const float4 xr4 = reinterpret_cast<const float4*>(x_real)[f4idx];
    const float4 xi4 = reinterpret_cast<const float4*>(x_imag)[f4idx];

    float xr[4] = {xr4.x, xr4.y, xr4.z, xr4.w};
    float xi[4] = {xi4.x, xi4.y, xi4.z, xi4.w};

    float s[4];
#pragma unroll
    for (int k = 0; k < 4; ++k)
        s[k] = fmaf(xr[k], xr[k], xi[k] * xi[k]);

    // f32x2 accumulators: lane0 = even centers, lane1 = odd centers.
    float arx[4], ary[4], aix[4], aiy[4];
#pragma unroll
    for (int k = 0; k < 4; ++k) { arx[k] = 0.0f; ary[k] = 0.0f; aix[k] = 0.0f; aiy[k] = 0.0f; }

#pragma unroll 4
    for (int p = 0; p < NPAIR; ++p) {
        const float4 A  = sA[p];
        const float4 Bv = sB[p];
        const float4 Wv = sW[p];

#pragma unroll
        for (int k = 0; k < 4; ++k) {
            float gx, gy;
            ffma2(gx, gy, s[k],  s[k],  A.x,  A.y,  Bv.z, Bv.w);  // a0*s + a3
            ffma2(gx, gy, xr[k], xr[k], A.z,  A.w,  gx,   gy);    // + a1*xr
            ffma2(gx, gy, xi[k], xi[k], Bv.x, Bv.y, gx,   gy);    // + a2*xi
            float rx = ex2(gx);
            float ry = ex2(gy);
            ffma2(arx[k], ary[k], rx, ry, Wv.x, Wv.y, arx[k], ary[k]);
            ffma2(aix[k], aiy[k], rx, ry, Wv.z, Wv.w, aix[k], aiy[k]);
        }
    }

    const float br = b_real[c];
    const float bi = b_imag[c];

    // Horizontal add (even+odd centers) + bias; two float4 stores (r,i interleaved).
    float4* out4 = reinterpret_cast<float4*>(out);
#pragma unroll
    for (int q = 0; q < 2; ++q) {
        float4 o;
        o.x = (arx[2*q]   + ary[2*q])   + br;
        o.y = (aix[2*q]   + aiy[2*q])   + bi;
        o.z = (arx[2*q+1] + ary[2*q+1]) + br;
        o.w = (aix[2*q+1] + aiy[2*q+1]) + bi;
        out4[pairBase + q] = o;
    }
}

extern "C" void kernel_launch(void* const* d_in, const int* in_sizes, int n_in,
                              void* d_out, int out_size) {
    const float* x_real  = (const float*)d_in[0];
    const float* x_imag  = (const float*)d_in[1];
    const float* w_real  = (const float*)d_in[2];
    const float* w_imag  = (const float*)d_in[3];
    const float* b_real  = (const float*)d_in[4];
    const float* b_imag  = (const float*)d_in[5];
    const float* mu_real = (const float*)d_in[6];
    const float* mu_imag = (const float*)d_in[7];
    const float* stddev  = (const float*)d_in[8];
    float* out = (float*)d_out;

    // 128 (b,c) pairs * 8 tiles = 1024 blocks; 128 threads; 4 pixels/thread
    cplx_gaussian_rbf_kernel<<<1024, 128>>>(
        x_real, x_imag, w_real, w_imag, b_real, b_imag,
        mu_real, mu_imag, stddev, out);
}

// round 8
// speedup vs baseline: 1.1830x; 1.0201x over previous
#include <cuda_runtime.h>

// Problem constants (fixed by the reference: B=4, C=32, H=64, W=64, NW=64)
#define NWC 64
#define NPAIR 32
#define HW_PIX 4096
#define CC 32

typedef unsigned long long u64;

// Packed f32x2 FMA with 64-bit register-pair operands (no per-call packing).
__device__ __forceinline__ u64 ffma2(u64 a, u64 b, u64 c) {
    u64 d;
    asm("fma.rn.f32x2 %0, %1, %2, %3;" : "=l"(d) : "l"(a), "l"(b), "l"(c));
    return d;
}

__device__ __forceinline__ u64 pack2(float x, float y) {
    u64 d;
    asm("mov.b64 %0, {%1, %2};" : "=l"(d) : "f"(x), "f"(y));
    return d;
}

__device__ __forceinline__ void unpack2(float& x, float& y, u64 d) {
    asm("mov.b64 {%0, %1}, %2;" : "=f"(x), "=f"(y) : "l"(d));
}

__device__ __forceinline__ float ex2(float a) {
    float r;
    asm("ex2.approx.ftz.f32 %0, %1;" : "=f"(r) : "f"(a));
    return r;
}

__global__ __launch_bounds__(128)
void cplx_gaussian_rbf_kernel(
    const float* __restrict__ x_real, const float* __restrict__ x_imag,
    const float* __restrict__ w_real, const float* __restrict__ w_imag,
    const float* __restrict__ b_real, const float* __restrict__ b_imag,
    const float* __restrict__ mu_real, const float* __restrict__ mu_imag,
    const float* __restrict__ stddev,
    float* __restrict__ out)
{
    // Center-pair coefficient tables, pre-packed as 64-bit f32x2 operands.
    // One LDS.128 yields two ready-to-use f32x2 registers.
    __shared__ ulonglong2 sA[NPAIR];  // {.x = (a0_e,a0_o), .y = (a1_e,a1_o)}
    __shared__ ulonglong2 sB[NPAIR];  // {.x = (a2_e,a2_o), .y = (a3_e,a3_o)}
    __shared__ ulonglong2 sW[NPAIR];  // {.x = (wr_e,wr_o), .y = (wi_e,wi_o)}

    const int bc   = blockIdx.x >> 3;        // (b*C + c), 0..127
    const int tile = blockIdx.x & 7;         // 8 tiles of 512 pixels per (b,c)
    const int c    = bc & (CC - 1);
    const int tid  = threadIdx.x;

    if (tid < NPAIR) {
        const float LOG2E = 1.4426950408889634f;
        const int n0 = 2 * tid, n1 = 2 * tid + 1;
        // exp(-d2/(2*sigma)) = exp2( a0*s + a1*xr + a2*xi + a3 ),  s = xr^2+xi^2
        float mur0 = mu_real[n0], mui0 = mu_imag[n0];
        float cc0  = LOG2E * 0.5f / stddev[n0];
        float mur1 = mu_real[n1], mui1 = mu_imag[n1];
        float cc1  = LOG2E * 0.5f / stddev[n1];
        ulonglong2 A, Bv, Wv;
        A.x  = pack2(-cc0, -cc1);
        A.y  = pack2(2.0f * cc0 * mur0, 2.0f * cc1 * mur1);
        Bv.x = pack2(2.0f * cc0 * mui0, 2.0f * cc1 * mui1);
        Bv.y = pack2(-cc0 * (mur0 * mur0 + mui0 * mui0),
                     -cc1 * (mur1 * mur1 + mui1 * mui1));
        Wv.x = pack2(w_real[c * NWC + n0], w_real[c * NWC + n1]);
        Wv.y = pack2(w_imag[c * NWC + n0], w_imag[c * NWC + n1]);
        sA[tid] = A;
        sB[tid] = Bv;
        sW[tid] = Wv;
    }
    __syncthreads();

    // 4 consecutive pixels per thread (one float4 load per input).
    const int f4idx    = bc * (HW_PIX / 4) + tile * 128 + tid;  // float4 units
    const int pairBase = f4idx * 2;                              // pixel-pair units

    const float4 xr4 = reinterpret_cast<const float4*>(x_real)[f4idx];
    const float4 xi4 = reinterpret_cast<const float4*>(x_imag)[f4idx];

    const float xr[4] = {xr4.x, xr4.y, xr4.z, xr4.w};
    const float xi[4] = {xi4.x, xi4.y, xi4.z, xi4.w};

    // Loop-invariant packed pixel operands (both lanes identical): packed ONCE.
    u64 sd[4], xrd[4], xid[4];
#pragma unroll
    for (int k = 0; k < 4; ++k) {
        float s = fmaf(xr[k], xr[k], xi[k] * xi[k]);
        sd[k]  = pack2(s, s);
        xrd[k] = pack2(xr[k], xr[k]);
        xid[k] = pack2(xi[k], xi[k]);
    }

    // f32x2 accumulators: lane0 = even centers, lane1 = odd centers.
    u64 accr[4], acci[4];
#pragma unroll
    for (int k = 0; k < 4; ++k) { accr[k] = 0ULL; acci[k] = 0ULL; }

#pragma unroll 4
    for (int p = 0; p < NPAIR; ++p) {
        const ulonglong2 A  = sA[p];
        const ulonglong2 Bv = sB[p];
        const ulonglong2 Wv = sW[p];

#pragma unroll
        for (int k = 0; k < 4; ++k) {
            u64 g = ffma2(sd[k],  A.x,  Bv.y);  // a0*s + a3
            g     = ffma2(xrd[k], A.y,  g);     // + a1*xr
            g     = ffma2(xid[k], Bv.x, g);     // + a2*xi
            float gx, gy;
            unpack2(gx, gy, g);
            u64 r = pack2(ex2(gx), ex2(gy));
            accr[k] = ffma2(r, Wv.x, accr[k]);
            acci[k] = ffma2(r, Wv.y, acci[k]);
        }
    }

    const float br = b_real[c];
    const float bi = b_imag[c];

    // Horizontal add (even+odd centers) + bias; two float4 stores (r,i interleaved).
    float4* out4 = reinterpret_cast<float4*>(out);
#pragma unroll
    for (int q = 0; q < 2; ++q) {
        float r0x, r0y, i0x, i0y, r1x, r1y, i1x, i1y;
        unpack2(r0x, r0y, accr[2*q]);
        unpack2(i0x, i0y, acci[2*q]);
        unpack2(r1x, r1y, accr[2*q+1]);
        unpack2(i1x, i1y, acci[2*q+1]);
        float4 o;
        o.x = (r0x + r0y) + br;
        o.y = (i0x + i0y) + bi;
        o.z = (r1x + r1y) + br;
        o.w = (i1x + i1y) + bi;
        out4[pairBase + q] = o;
    }
}

extern "C" void kernel_launch(void* const* d_in, const int* in_sizes, int n_in,
                              void* d_out, int out_size) {
    const float* x_real  = (const float*)d_in[0];
    const float* x_imag  = (const float*)d_in[1];
    const float* w_real  = (const float*)d_in[2];
    const float* w_imag  = (const float*)d_in[3];
    const float* b_real  = (const float*)d_in[4];
    const float* b_imag  = (const float*)d_in[5];
    const float* mu_real = (const float*)d_in[6];
    const float* mu_imag = (const float*)d_in[7];
    const float* stddev  = (const float*)d_in[8];
    float* out = (float*)d_out;

    // 128 (b,c) pairs * 8 tiles = 1024 blocks; 128 threads; 4 pixels/thread
    cplx_gaussian_rbf_kernel<<<1024, 128>>>(
        x_real, x_imag, w_real, w_imag, b_real, b_imag,
        mu_real, mu_imag, stddev, out);
}